// round 1
// baseline (speedup 1.0000x reference)
#include <cuda_runtime.h>

// loss = [2*N*sum(e^2) - 2*(sum e)^2] / (N*(N-1)),  e = pred - tgt
// Single-block two-moment reduction over N=16384 floats.

__global__ __launch_bounds__(1024, 1)
void rdl_kernel(const float* __restrict__ pred,
                const float* __restrict__ tgt,
                float* __restrict__ out, int n) {
    const int tid = threadIdx.x;
    const int nthreads = blockDim.x;

    float s1 = 0.0f, s2 = 0.0f;

    // Vectorized grid-stride over float4s (n is a multiple of 4: 16384)
    const float4* __restrict__ p4 = reinterpret_cast<const float4*>(pred);
    const float4* __restrict__ t4 = reinterpret_cast<const float4*>(tgt);
    const int n4 = n >> 2;

    #pragma unroll 4
    for (int i = tid; i < n4; i += nthreads) {
        float4 a = p4[i];
        float4 b = t4[i];
        float e0 = a.x - b.x;
        float e1 = a.y - b.y;
        float e2 = a.z - b.z;
        float e3 = a.w - b.w;
        s1 += (e0 + e1) + (e2 + e3);
        s2 += fmaf(e0, e0, fmaf(e1, e1, fmaf(e2, e2, e3 * e3)));
    }

    // Warp reduction
    #pragma unroll
    for (int off = 16; off > 0; off >>= 1) {
        s1 += __shfl_xor_sync(0xFFFFFFFFu, s1, off);
        s2 += __shfl_xor_sync(0xFFFFFFFFu, s2, off);
    }

    __shared__ float sh1[32], sh2[32];
    const int wid = tid >> 5;
    const int lid = tid & 31;
    if (lid == 0) { sh1[wid] = s1; sh2[wid] = s2; }
    __syncthreads();

    if (wid == 0) {
        const int nwarps = nthreads >> 5;
        float r1 = (lid < nwarps) ? sh1[lid] : 0.0f;
        float r2 = (lid < nwarps) ? sh2[lid] : 0.0f;
        #pragma unroll
        for (int off = 16; off > 0; off >>= 1) {
            r1 += __shfl_xor_sync(0xFFFFFFFFu, r1, off);
            r2 += __shfl_xor_sync(0xFFFFFFFFu, r2, off);
        }
        if (lid == 0) {
            float nf = (float)n;
            // (2*n*S2 - 2*S1^2) / (n*(n-1))
            float num = 2.0f * (nf * r2 - r1 * r1);
            float den = nf * (nf - 1.0f);
            out[0] = num / den;
        }
    }
}

extern "C" void kernel_launch(void* const* d_in, const int* in_sizes, int n_in,
                              void* d_out, int out_size) {
    const float* pred = (const float*)d_in[0];
    const float* tgt  = (const float*)d_in[1];
    float* out = (float*)d_out;
    int n = in_sizes[0];
    rdl_kernel<<<1, 1024>>>(pred, tgt, out, n);
}

// round 2
// speedup vs baseline: 1.0337x; 1.0337x over previous
#include <cuda_runtime.h>

// loss = 2*(N*sum(e^2) - (sum e)^2) / (N*(N-1)),  e = pred - tgt
// 32 blocks x 128 threads: each thread loads exactly one float4 from each
// input (32*128*4 = 16384 = N). Block partials -> device scratch; last block
// (threadfence-reduction pattern) combines 32 partials and writes the scalar.

#define NBLK 32
#define NTHR 128

__device__ float2 g_partial[NBLK];
__device__ unsigned int g_count = 0;

__global__ __launch_bounds__(NTHR, 1)
void rdl_kernel(const float* __restrict__ pred,
                const float* __restrict__ tgt,
                float* __restrict__ out, int n) {
    const int tid = threadIdx.x;
    const int gid = blockIdx.x * NTHR + tid;

    // One float4 from each array per thread; n = NBLK*NTHR*4 exactly (16384).
    const float4* __restrict__ p4 = reinterpret_cast<const float4*>(pred);
    const float4* __restrict__ t4 = reinterpret_cast<const float4*>(tgt);

    float s1 = 0.0f, s2 = 0.0f;
    const int n4 = n >> 2;
    if (gid < n4) {
        float4 a = p4[gid];
        float4 b = t4[gid];
        float e0 = a.x - b.x;
        float e1 = a.y - b.y;
        float e2 = a.z - b.z;
        float e3 = a.w - b.w;
        s1 = (e0 + e1) + (e2 + e3);
        s2 = fmaf(e0, e0, fmaf(e1, e1, fmaf(e2, e2, e3 * e3)));
    }

    // Warp reduction
    #pragma unroll
    for (int off = 16; off > 0; off >>= 1) {
        s1 += __shfl_xor_sync(0xFFFFFFFFu, s1, off);
        s2 += __shfl_xor_sync(0xFFFFFFFFu, s2, off);
    }

    __shared__ float sh1[4], sh2[4];
    const int wid = tid >> 5;
    const int lid = tid & 31;
    if (lid == 0) { sh1[wid] = s1; sh2[wid] = s2; }
    __syncthreads();

    __shared__ bool amLast;
    if (tid == 0) {
        float b1 = (sh1[0] + sh1[1]) + (sh1[2] + sh1[3]);
        float b2 = (sh2[0] + sh2[1]) + (sh2[2] + sh2[3]);
        g_partial[blockIdx.x] = make_float2(b1, b2);
        __threadfence();
        unsigned int prev = atomicAdd(&g_count, 1u);
        amLast = (prev == (unsigned int)(gridDim.x - 1));
    }
    __syncthreads();

    // Last block: one warp reduces the NBLK partials (fixed order -> deterministic)
    if (amLast && wid == 0) {
        float2 part = (lid < NBLK) ? g_partial[lid] : make_float2(0.0f, 0.0f);
        float r1 = part.x, r2 = part.y;
        #pragma unroll
        for (int off = 16; off > 0; off >>= 1) {
            r1 += __shfl_xor_sync(0xFFFFFFFFu, r1, off);
            r2 += __shfl_xor_sync(0xFFFFFFFFu, r2, off);
        }
        if (lid == 0) {
            float nf = (float)n;
            out[0] = 2.0f * (nf * r2 - r1 * r1) / (nf * (nf - 1.0f));
            g_count = 0;  // reset for next graph replay (deterministic)
        }
    }
}

extern "C" void kernel_launch(void* const* d_in, const int* in_sizes, int n_in,
                              void* d_out, int out_size) {
    const float* pred = (const float*)d_in[0];
    const float* tgt  = (const float*)d_in[1];
    float* out = (float*)d_out;
    int n = in_sizes[0];
    rdl_kernel<<<NBLK, NTHR>>>(pred, tgt, out, n);
}